// round 1
// baseline (speedup 1.0000x reference)
#include <cuda_runtime.h>
#include <math.h>
#include <stdint.h>

#define Bb 2
#define Ss 2048
#define Ee 1024
#define Hh 16
#define Dd 64
#define Mm (Bb*Ss)   // 4096

// Scratch (allocation-free rule: __device__ globals)
__device__ float g_q[Bb*Hh*Ss*Dd];
__device__ float g_k[Bb*Hh*Ss*Dd];
__device__ float g_v[Bb*Hh*Ss*Dd];
__device__ float g_ao[Bb*Ss*Ee];

// ---------------------------------------------------------------------------
// GEMM: out = X[M,1024] @ W[1024,1024]^T + bias
// mode 0: out[m*1024+n] row-major
// mode 1: scatter to [B,H,S,D]  (n -> (h,d), m -> (b,s))
// ---------------------------------------------------------------------------
__global__ __launch_bounds__(256, 2)
void gemm128(const float* __restrict__ X, const float* __restrict__ W,
             const float* __restrict__ bias, float* __restrict__ out, int mode)
{
    __shared__ float As[16][128];
    __shared__ float Bs[16][128];
    const int tid = threadIdx.x;
    const int tx = tid & 15, ty = tid >> 4;
    const int m0 = blockIdx.y * 128, n0 = blockIdx.x * 128;

    const int lrow = tid >> 1;        // 0..127
    const int lk   = (tid & 1) * 8;   // 0 or 8

    const float* Ag = X + (size_t)(m0 + lrow) * Ee + lk;
    const float* Bg = W + (size_t)(n0 + lrow) * Ee + lk;

    float acc[8][8];
    #pragma unroll
    for (int i = 0; i < 8; i++)
        #pragma unroll
        for (int j = 0; j < 8; j++) acc[i][j] = 0.f;

    for (int k0 = 0; k0 < Ee; k0 += 16) {
        float4 a0 = *(const float4*)(Ag + k0);
        float4 a1 = *(const float4*)(Ag + k0 + 4);
        float4 b0 = *(const float4*)(Bg + k0);
        float4 b1 = *(const float4*)(Bg + k0 + 4);
        __syncthreads();
        As[lk+0][lrow]=a0.x; As[lk+1][lrow]=a0.y; As[lk+2][lrow]=a0.z; As[lk+3][lrow]=a0.w;
        As[lk+4][lrow]=a1.x; As[lk+5][lrow]=a1.y; As[lk+6][lrow]=a1.z; As[lk+7][lrow]=a1.w;
        Bs[lk+0][lrow]=b0.x; Bs[lk+1][lrow]=b0.y; Bs[lk+2][lrow]=b0.z; Bs[lk+3][lrow]=b0.w;
        Bs[lk+4][lrow]=b1.x; Bs[lk+5][lrow]=b1.y; Bs[lk+6][lrow]=b1.z; Bs[lk+7][lrow]=b1.w;
        __syncthreads();
        #pragma unroll
        for (int kk = 0; kk < 16; kk++) {
            float4 av0 = *(const float4*)&As[kk][ty*8];
            float4 av1 = *(const float4*)&As[kk][ty*8+4];
            float4 bv0 = *(const float4*)&Bs[kk][tx*8];
            float4 bv1 = *(const float4*)&Bs[kk][tx*8+4];
            float a[8] = {av0.x,av0.y,av0.z,av0.w,av1.x,av1.y,av1.z,av1.w};
            float b[8] = {bv0.x,bv0.y,bv0.z,bv0.w,bv1.x,bv1.y,bv1.z,bv1.w};
            #pragma unroll
            for (int i = 0; i < 8; i++)
                #pragma unroll
                for (int j = 0; j < 8; j++)
                    acc[i][j] = fmaf(a[i], b[j], acc[i][j]);
        }
    }

    float bb[8];
    #pragma unroll
    for (int j = 0; j < 8; j++) bb[j] = bias[n0 + tx*8 + j];

    #pragma unroll
    for (int i = 0; i < 8; i++) {
        int m = m0 + ty*8 + i;
        float4 r0 = make_float4(acc[i][0]+bb[0], acc[i][1]+bb[1],
                                acc[i][2]+bb[2], acc[i][3]+bb[3]);
        float4 r1 = make_float4(acc[i][4]+bb[4], acc[i][5]+bb[5],
                                acc[i][6]+bb[6], acc[i][7]+bb[7]);
        float* dst;
        if (mode == 0) {
            dst = out + (size_t)m * Ee + n0 + tx*8;
        } else {
            int b = m >> 11, s = m & 2047;
            int n = n0 + tx*8;
            int h = n >> 6, d = n & 63;
            dst = out + (((size_t)(b*Hh + h) * Ss) + s) * Dd + d;
        }
        *(float4*)dst       = r0;
        *(float4*)(dst + 4) = r1;
    }
}

// ---------------------------------------------------------------------------
// RoPE in-place on [B,H,S,D] tensor. One thread per (row, pair j<32).
// fp64 trig: strictly more accurate than the fp32 reference cache.
// ---------------------------------------------------------------------------
__global__ __launch_bounds__(256)
void rope_kernel(float* __restrict__ p)
{
    int idx = blockIdx.x * 256 + threadIdx.x;     // < B*H*S*32
    int j   = idx & 31;
    int row = idx >> 5;                            // (b*H+h)*S + s
    int s   = row & (Ss - 1);
    float* base = p + (size_t)row * Dd;

    double inv = exp(-((double)(2 * j) / 64.0) * log(10000.0));
    double ang = (double)s * inv;
    double sd, cd;
    sincos(ang, &sd, &cd);
    float cs = (float)cd, sn = (float)sd;

    float x1 = base[j], x2 = base[j + 32];
    base[j]      = x1 * cs - x2 * sn;
    base[j + 32] = x2 * cs + x1 * sn;
}

// ---------------------------------------------------------------------------
// Flash attention fp32, causal.
// Block = (q-tile of 64 rows, one b*h). 256 threads, 4x4 microtile.
// Smem: Qt[d][r] swizzled, KtPt (K transposed, later aliased by P transposed),
// Vs[t][d] natural. 48 KB total.
// ---------------------------------------------------------------------------
__device__ __forceinline__ int swz(int d, int c) {
    return d * 64 + (((( (c >> 2) ^ ((d >> 2) & 15) )) << 2) | (c & 3));
}
__device__ __forceinline__ float4 ld4s(const float* base, int d, int cg) {
    return *(const float4*)(base + d * 64 + ((cg ^ ((d >> 2) & 15)) << 2));
}

__global__ __launch_bounds__(256)
void flash_kernel(const float* __restrict__ q, const float* __restrict__ k,
                  const float* __restrict__ v, float* __restrict__ out)
{
    extern __shared__ float sm[];
    float* Qt   = sm;            // 4096
    float* KtPt = sm + 4096;     // 4096 (K^T, reused as P^T)
    float* Vs   = sm + 8192;     // 4096

    const int tid = threadIdx.x;
    const int tx = tid & 15, ty = tid >> 4;
    const int qt = blockIdx.x, bh = blockIdx.y;
    const int q0 = qt * 64;

    const float* qg = q + ((size_t)bh * Ss + q0) * Dd;
    const float* kg = k + (size_t)bh * Ss * Dd;
    const float* vg = v + (size_t)bh * Ss * Dd;

    // Load Q tile transposed+swizzled (coalesced global reads)
    #pragma unroll
    for (int i = 0; i < 4; i++) {
        int f = i * 256 + tid;
        int c = f >> 4;             // q row in tile
        int d0 = (f & 15) * 4;
        float4 t4 = *(const float4*)(qg + c * 64 + d0);
        Qt[swz(d0+0, c)] = t4.x; Qt[swz(d0+1, c)] = t4.y;
        Qt[swz(d0+2, c)] = t4.z; Qt[swz(d0+3, c)] = t4.w;
    }

    float o[4][4];
    float mrow[4], lrow[4];
    #pragma unroll
    for (int i = 0; i < 4; i++) {
        mrow[i] = -1e30f; lrow[i] = 0.f;
        #pragma unroll
        for (int j = 0; j < 4; j++) o[i][j] = 0.f;
    }

    const int ntiles = qt + 1;
    for (int it = 0; it < ntiles; it++) {
        const int kv0 = it * 64;
        __syncthreads();
        // Load K (transposed+swizzled) and V (natural) tiles
        #pragma unroll
        for (int i = 0; i < 4; i++) {
            int f = i * 256 + tid;
            int c = f >> 4;
            int d0 = (f & 15) * 4;
            float4 kk4 = *(const float4*)(kg + (size_t)(kv0 + c) * 64 + d0);
            KtPt[swz(d0+0, c)] = kk4.x; KtPt[swz(d0+1, c)] = kk4.y;
            KtPt[swz(d0+2, c)] = kk4.z; KtPt[swz(d0+3, c)] = kk4.w;
            float4 vv4 = *(const float4*)(vg + (size_t)(kv0 + c) * 64 + d0);
            *(float4*)(Vs + c * 64 + d0) = vv4;
        }
        __syncthreads();

        // S = Q K^T (64x64x64), 4x4 per thread
        float acc[4][4];
        #pragma unroll
        for (int i = 0; i < 4; i++)
            #pragma unroll
            for (int j = 0; j < 4; j++) acc[i][j] = 0.f;

        #pragma unroll 16
        for (int dd = 0; dd < 64; dd++) {
            float4 a = ld4s(Qt, dd, ty);
            float4 b = ld4s(KtPt, dd, tx);
            acc[0][0] = fmaf(a.x, b.x, acc[0][0]); acc[0][1] = fmaf(a.x, b.y, acc[0][1]);
            acc[0][2] = fmaf(a.x, b.z, acc[0][2]); acc[0][3] = fmaf(a.x, b.w, acc[0][3]);
            acc[1][0] = fmaf(a.y, b.x, acc[1][0]); acc[1][1] = fmaf(a.y, b.y, acc[1][1]);
            acc[1][2] = fmaf(a.y, b.z, acc[1][2]); acc[1][3] = fmaf(a.y, b.w, acc[1][3]);
            acc[2][0] = fmaf(a.z, b.x, acc[2][0]); acc[2][1] = fmaf(a.z, b.y, acc[2][1]);
            acc[2][2] = fmaf(a.z, b.z, acc[2][2]); acc[2][3] = fmaf(a.z, b.w, acc[2][3]);
            acc[3][0] = fmaf(a.w, b.x, acc[3][0]); acc[3][1] = fmaf(a.w, b.y, acc[3][1]);
            acc[3][2] = fmaf(a.w, b.z, acc[3][2]); acc[3][3] = fmaf(a.w, b.w, acc[3][3]);
        }

        const bool diag = (it == qt);
        #pragma unroll
        for (int i = 0; i < 4; i++)
            #pragma unroll
            for (int j = 0; j < 4; j++) {
                float sc = acc[i][j] * 0.125f;   // 1/sqrt(64)
                if (diag && (kv0 + tx*4 + j) > (q0 + ty*4 + i)) sc = -1e30f;
                acc[i][j] = sc;
            }

        // Online softmax (per-row state replicated across the 16 tx lanes)
        float fac[4];
        #pragma unroll
        for (int i = 0; i < 4; i++) {
            float r = fmaxf(fmaxf(acc[i][0], acc[i][1]), fmaxf(acc[i][2], acc[i][3]));
            #pragma unroll
            for (int off = 1; off < 16; off <<= 1)
                r = fmaxf(r, __shfl_xor_sync(0xffffffffu, r, off));
            float mnew = fmaxf(mrow[i], r);
            fac[i] = __expf(mrow[i] - mnew);
            #pragma unroll
            for (int j = 0; j < 4; j++) acc[i][j] = __expf(acc[i][j] - mnew);
            float rs = acc[i][0] + acc[i][1] + acc[i][2] + acc[i][3];
            #pragma unroll
            for (int off = 1; off < 16; off <<= 1)
                rs += __shfl_xor_sync(0xffffffffu, rs, off);
            lrow[i] = lrow[i] * fac[i] + rs;
            mrow[i] = mnew;
            #pragma unroll
            for (int j = 0; j < 4; j++) o[i][j] *= fac[i];
        }

        __syncthreads();   // all Kt reads done before overwriting with P^T
        // Write P^T into KtPt: Pt[t][r], float4 along r
        #pragma unroll
        for (int jj = 0; jj < 4; jj++) {
            int t = tx * 4 + jj;
            float4 pv = make_float4(acc[0][jj], acc[1][jj], acc[2][jj], acc[3][jj]);
            *(float4*)(KtPt + t * 64 + ((ty ^ ((t >> 2) & 15)) << 2)) = pv;
        }
        __syncthreads();

        // O += P V (64x64x64)
        #pragma unroll 16
        for (int t = 0; t < 64; t++) {
            float4 a = ld4s(KtPt, t, ty);
            float4 b = *(const float4*)(Vs + t * 64 + tx * 4);
            o[0][0] = fmaf(a.x, b.x, o[0][0]); o[0][1] = fmaf(a.x, b.y, o[0][1]);
            o[0][2] = fmaf(a.x, b.z, o[0][2]); o[0][3] = fmaf(a.x, b.w, o[0][3]);
            o[1][0] = fmaf(a.y, b.x, o[1][0]); o[1][1] = fmaf(a.y, b.y, o[1][1]);
            o[1][2] = fmaf(a.y, b.z, o[1][2]); o[1][3] = fmaf(a.y, b.w, o[1][3]);
            o[2][0] = fmaf(a.z, b.x, o[2][0]); o[2][1] = fmaf(a.z, b.y, o[2][1]);
            o[2][2] = fmaf(a.z, b.z, o[2][2]); o[2][3] = fmaf(a.z, b.w, o[2][3]);
            o[3][0] = fmaf(a.w, b.x, o[3][0]); o[3][1] = fmaf(a.w, b.y, o[3][1]);
            o[3][2] = fmaf(a.w, b.z, o[3][2]); o[3][3] = fmaf(a.w, b.w, o[3][3]);
        }
    }

    // Normalize + write to [B,S,E] (b, s, h*64+d)
    const int b = bh >> 4, h = bh & 15;
    #pragma unroll
    for (int i = 0; i < 4; i++) {
        int s = q0 + ty * 4 + i;
        float il = 1.0f / lrow[i];
        float4 r = make_float4(o[i][0]*il, o[i][1]*il, o[i][2]*il, o[i][3]*il);
        *(float4*)(out + ((size_t)(b * Ss + s)) * Ee + h * 64 + tx * 4) = r;
    }
}

// ---------------------------------------------------------------------------
extern "C" void kernel_launch(void* const* d_in, const int* in_sizes, int n_in,
                              void* d_out, int out_size)
{
    (void)in_sizes; (void)n_in; (void)out_size;
    const float* query = (const float*)d_in[0];
    const float* key   = (const float*)d_in[1];
    const float* value = (const float*)d_in[2];
    const float* Wq = (const float*)d_in[3];
    const float* bq = (const float*)d_in[4];
    const float* Wk = (const float*)d_in[5];
    const float* bk = (const float*)d_in[6];
    const float* Wv = (const float*)d_in[7];
    const float* bv = (const float*)d_in[8];
    const float* Wo = (const float*)d_in[9];
    const float* bo = (const float*)d_in[10];
    float* out = (float*)d_out;

    float *qp, *kp, *vp, *aop;
    cudaGetSymbolAddress((void**)&qp,  g_q);
    cudaGetSymbolAddress((void**)&kp,  g_k);
    cudaGetSymbolAddress((void**)&vp,  g_v);
    cudaGetSymbolAddress((void**)&aop, g_ao);

    static bool attr_set = false;
    if (!attr_set) {
        cudaFuncSetAttribute(flash_kernel,
                             cudaFuncAttributeMaxDynamicSharedMemorySize, 49152);
        attr_set = true;
    }

    dim3 gg(Ee / 128, Mm / 128);   // (8, 32)
    gemm128<<<gg, 256>>>(query, Wq, bq, qp, 1);
    gemm128<<<gg, 256>>>(key,   Wk, bk, kp, 1);
    gemm128<<<gg, 256>>>(value, Wv, bv, vp, 1);

    int ropeN = Bb * Hh * Ss * 32;     // 2097152
    rope_kernel<<<ropeN / 256, 256>>>(qp);
    rope_kernel<<<ropeN / 256, 256>>>(kp);

    flash_kernel<<<dim3(Ss / 64, Bb * Hh), 256, 49152>>>(qp, kp, vp, aop);

    gemm128<<<gg, 256>>>(aop, Wo, bo, out, 0);
}

// round 2
// speedup vs baseline: 1.3554x; 1.3554x over previous
#include <cuda_runtime.h>
#include <math.h>
#include <stdint.h>

#define Bb 2
#define Ss 2048
#define Ee 1024
#define Hh 16
#define Dd 64
#define Mm (Bb*Ss)   // 4096

// Scratch (allocation-free rule: __device__ globals)
__device__ float g_q[Bb*Hh*Ss*Dd];
__device__ float g_k[Bb*Hh*Ss*Dd];
__device__ float g_v[Bb*Hh*Ss*Dd];
__device__ float g_ao[Bb*Ss*Ee];
__device__ float g_cos[Ss*32];
__device__ float g_sin[Ss*32];

// ---------------------------------------------------------------------------
// GEMM: out = X[M,1024] @ W[1024,1024]^T + bias
// mode 0: out[m*1024+n] row-major
// mode 1: scatter to [B,H,S,D]  (n -> (h,d), m -> (b,s))
// ---------------------------------------------------------------------------
__global__ __launch_bounds__(256, 2)
void gemm128(const float* __restrict__ X, const float* __restrict__ W,
             const float* __restrict__ bias, float* __restrict__ out, int mode)
{
    __shared__ float As[16][128];
    __shared__ float Bs[16][128];
    const int tid = threadIdx.x;
    const int tx = tid & 15, ty = tid >> 4;
    const int m0 = blockIdx.y * 128, n0 = blockIdx.x * 128;

    const int lrow = tid >> 1;        // 0..127
    const int lk   = (tid & 1) * 8;   // 0 or 8

    const float* Ag = X + (size_t)(m0 + lrow) * Ee + lk;
    const float* Bg = W + (size_t)(n0 + lrow) * Ee + lk;

    float acc[8][8];
    #pragma unroll
    for (int i = 0; i < 8; i++)
        #pragma unroll
        for (int j = 0; j < 8; j++) acc[i][j] = 0.f;

    for (int k0 = 0; k0 < Ee; k0 += 16) {
        float4 a0 = *(const float4*)(Ag + k0);
        float4 a1 = *(const float4*)(Ag + k0 + 4);
        float4 b0 = *(const float4*)(Bg + k0);
        float4 b1 = *(const float4*)(Bg + k0 + 4);
        __syncthreads();
        As[lk+0][lrow]=a0.x; As[lk+1][lrow]=a0.y; As[lk+2][lrow]=a0.z; As[lk+3][lrow]=a0.w;
        As[lk+4][lrow]=a1.x; As[lk+5][lrow]=a1.y; As[lk+6][lrow]=a1.z; As[lk+7][lrow]=a1.w;
        Bs[lk+0][lrow]=b0.x; Bs[lk+1][lrow]=b0.y; Bs[lk+2][lrow]=b0.z; Bs[lk+3][lrow]=b0.w;
        Bs[lk+4][lrow]=b1.x; Bs[lk+5][lrow]=b1.y; Bs[lk+6][lrow]=b1.z; Bs[lk+7][lrow]=b1.w;
        __syncthreads();
        #pragma unroll
        for (int kk = 0; kk < 16; kk++) {
            float4 av0 = *(const float4*)&As[kk][ty*8];
            float4 av1 = *(const float4*)&As[kk][ty*8+4];
            float4 bv0 = *(const float4*)&Bs[kk][tx*8];
            float4 bv1 = *(const float4*)&Bs[kk][tx*8+4];
            float a[8] = {av0.x,av0.y,av0.z,av0.w,av1.x,av1.y,av1.z,av1.w};
            float b[8] = {bv0.x,bv0.y,bv0.z,bv0.w,bv1.x,bv1.y,bv1.z,bv1.w};
            #pragma unroll
            for (int i = 0; i < 8; i++)
                #pragma unroll
                for (int j = 0; j < 8; j++)
                    acc[i][j] = fmaf(a[i], b[j], acc[i][j]);
        }
    }

    float bb[8];
    #pragma unroll
    for (int j = 0; j < 8; j++) bb[j] = bias[n0 + tx*8 + j];

    #pragma unroll
    for (int i = 0; i < 8; i++) {
        int m = m0 + ty*8 + i;
        float4 r0 = make_float4(acc[i][0]+bb[0], acc[i][1]+bb[1],
                                acc[i][2]+bb[2], acc[i][3]+bb[3]);
        float4 r1 = make_float4(acc[i][4]+bb[4], acc[i][5]+bb[5],
                                acc[i][6]+bb[6], acc[i][7]+bb[7]);
        float* dst;
        if (mode == 0) {
            dst = out + (size_t)m * Ee + n0 + tx*8;
        } else {
            int b = m >> 11, s = m & 2047;
            int n = n0 + tx*8;
            int h = n >> 6, d = n & 63;
            dst = out + (((size_t)(b*Hh + h) * Ss) + s) * Dd + d;
        }
        *(float4*)dst       = r0;
        *(float4*)(dst + 4) = r1;
    }
}

// ---------------------------------------------------------------------------
// RoPE: tiny table kernel (fp64 trig, 65536 threads) + memory-bound apply.
// ---------------------------------------------------------------------------
__global__ __launch_bounds__(256)
void rope_table_kernel(float* __restrict__ cosT, float* __restrict__ sinT)
{
    int idx = blockIdx.x * 256 + threadIdx.x;   // < Ss*32
    int j = idx & 31;
    int s = idx >> 5;
    double inv = exp(-((double)(2 * j) / 64.0) * log(10000.0));
    double sd, cd;
    sincos((double)s * inv, &sd, &cd);
    cosT[idx] = (float)cd;
    sinT[idx] = (float)sd;
}

// One thread per (row, 4-pair group). blockIdx.y selects q or k.
__global__ __launch_bounds__(256)
void rope_apply_kernel(float* __restrict__ q, float* __restrict__ k,
                       const float* __restrict__ cosT, const float* __restrict__ sinT)
{
    int idx = blockIdx.x * 256 + threadIdx.x;   // < B*H*S*8
    int jg  = (idx & 7) * 4;
    int row = idx >> 3;                          // (b*H+h)*S + s
    int s   = row & (Ss - 1);
    float* base = (blockIdx.y == 0 ? q : k) + (size_t)row * Dd;

    float4 c = *(const float4*)(cosT + s * 32 + jg);
    float4 sn = *(const float4*)(sinT + s * 32 + jg);
    float4 x1 = *(const float4*)(base + jg);
    float4 x2 = *(const float4*)(base + jg + 32);

    float4 r1, r2;
    r1.x = x1.x*c.x - x2.x*sn.x;  r2.x = x2.x*c.x + x1.x*sn.x;
    r1.y = x1.y*c.y - x2.y*sn.y;  r2.y = x2.y*c.y + x1.y*sn.y;
    r1.z = x1.z*c.z - x2.z*sn.z;  r2.z = x2.z*c.z + x1.z*sn.z;
    r1.w = x1.w*c.w - x2.w*sn.w;  r2.w = x2.w*c.w + x1.w*sn.w;

    *(float4*)(base + jg)      = r1;
    *(float4*)(base + jg + 32) = r2;
}

// ---------------------------------------------------------------------------
// Flash attention fp32, causal.
// Block = (q-tile of 64 rows, one b*h). 256 threads, 4x4 microtile.
// ---------------------------------------------------------------------------
__device__ __forceinline__ int swz(int d, int c) {
    return d * 64 + (((( (c >> 2) ^ ((d >> 2) & 15) )) << 2) | (c & 3));
}
__device__ __forceinline__ float4 ld4s(const float* base, int d, int cg) {
    return *(const float4*)(base + d * 64 + ((cg ^ ((d >> 2) & 15)) << 2));
}

__global__ __launch_bounds__(256)
void flash_kernel(const float* __restrict__ q, const float* __restrict__ k,
                  const float* __restrict__ v, float* __restrict__ out)
{
    extern __shared__ float sm[];
    float* Qt   = sm;            // 4096
    float* KtPt = sm + 4096;     // 4096 (K^T, reused as P^T)
    float* Vs   = sm + 8192;     // 4096

    const int tid = threadIdx.x;
    const int tx = tid & 15, ty = tid >> 4;
    const int qt = blockIdx.x, bh = blockIdx.y;
    const int q0 = qt * 64;

    const float* qg = q + ((size_t)bh * Ss + q0) * Dd;
    const float* kg = k + (size_t)bh * Ss * Dd;
    const float* vg = v + (size_t)bh * Ss * Dd;

    #pragma unroll
    for (int i = 0; i < 4; i++) {
        int f = i * 256 + tid;
        int c = f >> 4;
        int d0 = (f & 15) * 4;
        float4 t4 = *(const float4*)(qg + c * 64 + d0);
        Qt[swz(d0+0, c)] = t4.x; Qt[swz(d0+1, c)] = t4.y;
        Qt[swz(d0+2, c)] = t4.z; Qt[swz(d0+3, c)] = t4.w;
    }

    float o[4][4];
    float mrow[4], lrow[4];
    #pragma unroll
    for (int i = 0; i < 4; i++) {
        mrow[i] = -1e30f; lrow[i] = 0.f;
        #pragma unroll
        for (int j = 0; j < 4; j++) o[i][j] = 0.f;
    }

    const int ntiles = qt + 1;
    for (int it = 0; it < ntiles; it++) {
        const int kv0 = it * 64;
        __syncthreads();
        #pragma unroll
        for (int i = 0; i < 4; i++) {
            int f = i * 256 + tid;
            int c = f >> 4;
            int d0 = (f & 15) * 4;
            float4 kk4 = *(const float4*)(kg + (size_t)(kv0 + c) * 64 + d0);
            KtPt[swz(d0+0, c)] = kk4.x; KtPt[swz(d0+1, c)] = kk4.y;
            KtPt[swz(d0+2, c)] = kk4.z; KtPt[swz(d0+3, c)] = kk4.w;
            float4 vv4 = *(const float4*)(vg + (size_t)(kv0 + c) * 64 + d0);
            *(float4*)(Vs + c * 64 + d0) = vv4;
        }
        __syncthreads();

        float acc[4][4];
        #pragma unroll
        for (int i = 0; i < 4; i++)
            #pragma unroll
            for (int j = 0; j < 4; j++) acc[i][j] = 0.f;

        #pragma unroll 16
        for (int dd = 0; dd < 64; dd++) {
            float4 a = ld4s(Qt, dd, ty);
            float4 b = ld4s(KtPt, dd, tx);
            acc[0][0] = fmaf(a.x, b.x, acc[0][0]); acc[0][1] = fmaf(a.x, b.y, acc[0][1]);
            acc[0][2] = fmaf(a.x, b.z, acc[0][2]); acc[0][3] = fmaf(a.x, b.w, acc[0][3]);
            acc[1][0] = fmaf(a.y, b.x, acc[1][0]); acc[1][1] = fmaf(a.y, b.y, acc[1][1]);
            acc[1][2] = fmaf(a.y, b.z, acc[1][2]); acc[1][3] = fmaf(a.y, b.w, acc[1][3]);
            acc[2][0] = fmaf(a.z, b.x, acc[2][0]); acc[2][1] = fmaf(a.z, b.y, acc[2][1]);
            acc[2][2] = fmaf(a.z, b.z, acc[2][2]); acc[2][3] = fmaf(a.z, b.w, acc[2][3]);
            acc[3][0] = fmaf(a.w, b.x, acc[3][0]); acc[3][1] = fmaf(a.w, b.y, acc[3][1]);
            acc[3][2] = fmaf(a.w, b.z, acc[3][2]); acc[3][3] = fmaf(a.w, b.w, acc[3][3]);
        }

        const bool diag = (it == qt);
        #pragma unroll
        for (int i = 0; i < 4; i++)
            #pragma unroll
            for (int j = 0; j < 4; j++) {
                float sc = acc[i][j] * 0.125f;
                if (diag && (kv0 + tx*4 + j) > (q0 + ty*4 + i)) sc = -1e30f;
                acc[i][j] = sc;
            }

        float fac[4];
        #pragma unroll
        for (int i = 0; i < 4; i++) {
            float r = fmaxf(fmaxf(acc[i][0], acc[i][1]), fmaxf(acc[i][2], acc[i][3]));
            #pragma unroll
            for (int off = 1; off < 16; off <<= 1)
                r = fmaxf(r, __shfl_xor_sync(0xffffffffu, r, off));
            float mnew = fmaxf(mrow[i], r);
            fac[i] = __expf(mrow[i] - mnew);
            #pragma unroll
            for (int j = 0; j < 4; j++) acc[i][j] = __expf(acc[i][j] - mnew);
            float rs = acc[i][0] + acc[i][1] + acc[i][2] + acc[i][3];
            #pragma unroll
            for (int off = 1; off < 16; off <<= 1)
                rs += __shfl_xor_sync(0xffffffffu, rs, off);
            lrow[i] = lrow[i] * fac[i] + rs;
            mrow[i] = mnew;
            #pragma unroll
            for (int j = 0; j < 4; j++) o[i][j] *= fac[i];
        }

        __syncthreads();
        #pragma unroll
        for (int jj = 0; jj < 4; jj++) {
            int t = tx * 4 + jj;
            float4 pv = make_float4(acc[0][jj], acc[1][jj], acc[2][jj], acc[3][jj]);
            *(float4*)(KtPt + t * 64 + ((ty ^ ((t >> 2) & 15)) << 2)) = pv;
        }
        __syncthreads();

        #pragma unroll 16
        for (int t = 0; t < 64; t++) {
            float4 a = ld4s(KtPt, t, ty);
            float4 b = *(const float4*)(Vs + t * 64 + tx * 4);
            o[0][0] = fmaf(a.x, b.x, o[0][0]); o[0][1] = fmaf(a.x, b.y, o[0][1]);
            o[0][2] = fmaf(a.x, b.z, o[0][2]); o[0][3] = fmaf(a.x, b.w, o[0][3]);
            o[1][0] = fmaf(a.y, b.x, o[1][0]); o[1][1] = fmaf(a.y, b.y, o[1][1]);
            o[1][2] = fmaf(a.y, b.z, o[1][2]); o[1][3] = fmaf(a.y, b.w, o[1][3]);
            o[2][0] = fmaf(a.z, b.x, o[2][0]); o[2][1] = fmaf(a.z, b.y, o[2][1]);
            o[2][2] = fmaf(a.z, b.z, o[2][2]); o[2][3] = fmaf(a.z, b.w, o[2][3]);
            o[3][0] = fmaf(a.w, b.x, o[3][0]); o[3][1] = fmaf(a.w, b.y, o[3][1]);
            o[3][2] = fmaf(a.w, b.z, o[3][2]); o[3][3] = fmaf(a.w, b.w, o[3][3]);
        }
    }

    const int b = bh >> 4, h = bh & 15;
    #pragma unroll
    for (int i = 0; i < 4; i++) {
        int s = q0 + ty * 4 + i;
        float il = 1.0f / lrow[i];
        float4 r = make_float4(o[i][0]*il, o[i][1]*il, o[i][2]*il, o[i][3]*il);
        *(float4*)(out + ((size_t)(b * Ss + s)) * Ee + h * 64 + tx * 4) = r;
    }
}

// ---------------------------------------------------------------------------
extern "C" void kernel_launch(void* const* d_in, const int* in_sizes, int n_in,
                              void* d_out, int out_size)
{
    (void)in_sizes; (void)n_in; (void)out_size;
    const float* query = (const float*)d_in[0];
    const float* key   = (const float*)d_in[1];
    const float* value = (const float*)d_in[2];
    const float* Wq = (const float*)d_in[3];
    const float* bq = (const float*)d_in[4];
    const float* Wk = (const float*)d_in[5];
    const float* bk = (const float*)d_in[6];
    const float* Wv = (const float*)d_in[7];
    const float* bv = (const float*)d_in[8];
    const float* Wo = (const float*)d_in[9];
    const float* bo = (const float*)d_in[10];
    float* out = (float*)d_out;

    float *qp, *kp, *vp, *aop, *ct, *st;
    cudaGetSymbolAddress((void**)&qp,  g_q);
    cudaGetSymbolAddress((void**)&kp,  g_k);
    cudaGetSymbolAddress((void**)&vp,  g_v);
    cudaGetSymbolAddress((void**)&aop, g_ao);
    cudaGetSymbolAddress((void**)&ct,  g_cos);
    cudaGetSymbolAddress((void**)&st,  g_sin);

    static bool attr_set = false;
    if (!attr_set) {
        cudaFuncSetAttribute(flash_kernel,
                             cudaFuncAttributeMaxDynamicSharedMemorySize, 49152);
        attr_set = true;
    }

    // RoPE table (independent of projections; launch first to overlap nothing critical)
    rope_table_kernel<<<(Ss * 32) / 256, 256>>>(ct, st);

    dim3 gg(Ee / 128, Mm / 128);   // (8, 32)
    gemm128<<<gg, 256>>>(query, Wq, bq, qp, 1);
    gemm128<<<gg, 256>>>(key,   Wk, bk, kp, 1);
    gemm128<<<gg, 256>>>(value, Wv, bv, vp, 1);

    // Fused RoPE apply for q and k
    int ropeBlocks = (Bb * Hh * Ss * 8) / 256;   // 2048
    rope_apply_kernel<<<dim3(ropeBlocks, 2), 256>>>(qp, kp, ct, st);

    flash_kernel<<<dim3(Ss / 64, Bb * Hh), 256, 49152>>>(qp, kp, vp, aop);

    gemm128<<<gg, 256>>>(aop, Wo, bo, out, 0);
}

// round 6
// speedup vs baseline: 2.2098x; 1.6303x over previous
#include <cuda_runtime.h>
#include <cuda_bf16.h>
#include <math.h>
#include <stdint.h>

#define Bb 2
#define Ss 2048
#define Ee 1024
#define Hh 16
#define Dd 64
#define Mm (Bb*Ss)   // 4096

// Scratch (allocation-free rule: __device__ globals)
__device__ float g_q[Bb*Hh*Ss*Dd];
__device__ float g_k[Bb*Hh*Ss*Dd];
__device__ float g_v[Bb*Hh*Ss*Dd];
__device__ float g_ao[Bb*Ss*Ee];
__device__ float g_cos[Ss*32];
__device__ float g_sin[Ss*32];
__device__ __nv_bfloat16 g_xh[Mm*Ee];
__device__ __nv_bfloat16 g_xl[Mm*Ee];
__device__ __nv_bfloat16 g_wh[Ee*Ee];
__device__ __nv_bfloat16 g_wl[Ee*Ee];

// ---------------------------------------------------------------------------
// Helpers (plain sm_80-class PTX only: mma.sync / ldmatrix / cp.async)
// ---------------------------------------------------------------------------
__device__ __forceinline__ uint32_t smem_to_u32(const void* p) {
    uint32_t a;
    asm("{ .reg .u64 t; cvta.to.shared.u64 t, %1; cvt.u32.u64 %0, t; }" : "=r"(a) : "l"(p));
    return a;
}
#define CP_ASYNC16(dst, src) \
    asm volatile("cp.async.cg.shared.global [%0], [%1], 16;" :: "r"(dst), "l"(src))
#define CP_ASYNC_COMMIT() asm volatile("cp.async.commit_group;" ::: "memory")
#define CP_ASYNC_WAIT0()  asm volatile("cp.async.wait_group 0;" ::: "memory")
#define SWZ128(o) ((o) ^ (((o) >> 3) & 0x70))

#define LDSM4(r, addr) \
    asm volatile("ldmatrix.sync.aligned.m8n8.x4.shared.b16 {%0,%1,%2,%3}, [%4];" \
        : "=r"((r)[0]), "=r"((r)[1]), "=r"((r)[2]), "=r"((r)[3]) : "r"(addr))

#define MMA16816(c, a, b0, b1) \
    asm volatile("mma.sync.aligned.m16n8k16.row.col.f32.bf16.bf16.f32 " \
        "{%0,%1,%2,%3},{%4,%5,%6,%7},{%8,%9},{%0,%1,%2,%3};" \
        : "+f"((c)[0]), "+f"((c)[1]), "+f"((c)[2]), "+f"((c)[3]) \
        : "r"((a)[0]), "r"((a)[1]), "r"((a)[2]), "r"((a)[3]), "r"(b0), "r"(b1))

// ---------------------------------------------------------------------------
// Split fp32 -> (hi, lo) bf16. One thread per 4 elements.
// ---------------------------------------------------------------------------
__global__ __launch_bounds__(256)
void split_kernel(const float* __restrict__ x, __nv_bfloat16* __restrict__ hi,
                  __nv_bfloat16* __restrict__ lo)
{
    int i = blockIdx.x * 256 + threadIdx.x;
    float4 v = ((const float4*)x)[i];
    __nv_bfloat16 h0 = __float2bfloat16(v.x), h1 = __float2bfloat16(v.y);
    __nv_bfloat16 h2 = __float2bfloat16(v.z), h3 = __float2bfloat16(v.w);
    __nv_bfloat16 l0 = __float2bfloat16(v.x - __bfloat162float(h0));
    __nv_bfloat16 l1 = __float2bfloat16(v.y - __bfloat162float(h1));
    __nv_bfloat16 l2 = __float2bfloat16(v.z - __bfloat162float(h2));
    __nv_bfloat16 l3 = __float2bfloat16(v.w - __bfloat162float(h3));
    ((__nv_bfloat162*)hi)[i*2]   = __nv_bfloat162(h0, h1);
    ((__nv_bfloat162*)hi)[i*2+1] = __nv_bfloat162(h2, h3);
    ((__nv_bfloat162*)lo)[i*2]   = __nv_bfloat162(l0, l1);
    ((__nv_bfloat162*)lo)[i*2+1] = __nv_bfloat162(l2, l3);
}

// ---------------------------------------------------------------------------
// HMMA GEMM: out[4096,1024] = X @ W^T + bias, bf16 3-term split (hh+lh+hl).
// CTA tile 128x128, K-chunk 64. 8 warps in 2x4 grid, warp tile 64x32.
// mode 0: row-major out; mode 1: scatter to [B,H,S,D].
// ---------------------------------------------------------------------------
#define TG_SMEM 65536

__global__ __launch_bounds__(256, 2)
void tgemm(const __nv_bfloat16* __restrict__ Ahp, const __nv_bfloat16* __restrict__ Alp,
           const __nv_bfloat16* __restrict__ Bhp, const __nv_bfloat16* __restrict__ Blp,
           const float* __restrict__ bias, float* __restrict__ out, int mode)
{
    extern __shared__ char smem[];
    uint32_t sb = smem_to_u32(smem);
    const int tid = threadIdx.x;
    const int lane = tid & 31, wid = tid >> 5;
    const int m0 = blockIdx.y * 128, n0 = blockIdx.x * 128;
    const int wm = (wid >> 2) * 64, wn = (wid & 3) * 32;

    const uint32_t sA  = sb;
    const uint32_t sAl = sb + 16384;
    const uint32_t sB  = sb + 32768;
    const uint32_t sBl = sb + 49152;

    float acc[4][4][4];
    #pragma unroll
    for (int mt = 0; mt < 4; mt++)
        #pragma unroll
        for (int nt = 0; nt < 4; nt++)
            #pragma unroll
            for (int r = 0; r < 4; r++) acc[mt][nt][r] = 0.f;

    // ldmatrix lane addressing
    const int lr = lane & 15;                       // A: row within 16-tile
    const uint32_t akb = (lane >> 4) * 16;          // A: k-byte sub-offset
    const uint32_t xrA = (uint32_t)(lr & 7) << 4;   // swizzle xor (row-derived)
    const int brow = (lane & 7) + ((lane >> 1) & 8);// B: row within 16 (2 n-tiles)
    const uint32_t bkb = (uint32_t)(lane & 8) * 2;  // B: k-byte sub-offset
    const uint32_t xrB = (uint32_t)(lane & 7) << 4;

    uint32_t aoff[4], boff[2];
    #pragma unroll
    for (int mt = 0; mt < 4; mt++) aoff[mt] = (uint32_t)(wm + mt * 16 + lr) * 128;
    #pragma unroll
    for (int h = 0; h < 2; h++)    boff[h]  = (uint32_t)(wn + h * 16 + brow) * 128;

    const char* srcs[4] = {(const char*)Ahp, (const char*)Alp,
                           (const char*)Bhp, (const char*)Blp};
    const uint32_t dsts[4] = {sA, sAl, sB, sBl};
    const int r0s[4] = {m0, m0, n0, n0};

    for (int kc = 0; kc < 16; kc++) {
        if (kc) __syncthreads();     // previous chunk's reads complete
        #pragma unroll
        for (int arr = 0; arr < 4; arr++) {
            #pragma unroll
            for (int i = 0; i < 4; i++) {
                int p = i * 256 + tid;
                int r = p >> 3, c = (p & 7) * 16;
                uint32_t dst = dsts[arr] + SWZ128((uint32_t)(r * 128 + c));
                const char* src = srcs[arr] + ((size_t)(r0s[arr] + r)) * 2048
                                  + kc * 128 + c;
                CP_ASYNC16(dst, src);
            }
        }
        CP_ASYNC_COMMIT();
        CP_ASYNC_WAIT0();
        __syncthreads();

        #pragma unroll
        for (int s = 0; s < 4; s++) {
            const uint32_t kA = ((uint32_t)(s * 32) + akb) ^ xrA;
            const uint32_t kB = ((uint32_t)(s * 32) + bkb) ^ xrB;

            uint32_t ah[4][4], bh[2][4];
            #pragma unroll
            for (int mt = 0; mt < 4; mt++) LDSM4(ah[mt], sA + aoff[mt] + kA);
            #pragma unroll
            for (int h = 0; h < 2; h++)    LDSM4(bh[h],  sB + boff[h] + kB);

            // hh
            #pragma unroll
            for (int mt = 0; mt < 4; mt++)
                #pragma unroll
                for (int nt = 0; nt < 4; nt++)
                    MMA16816(acc[mt][nt], ah[mt], bh[nt>>1][(nt&1)*2], bh[nt>>1][(nt&1)*2+1]);

            // lh (Al x Bh)
            {
                uint32_t al[4][4];
                #pragma unroll
                for (int mt = 0; mt < 4; mt++) LDSM4(al[mt], sAl + aoff[mt] + kA);
                #pragma unroll
                for (int mt = 0; mt < 4; mt++)
                    #pragma unroll
                    for (int nt = 0; nt < 4; nt++)
                        MMA16816(acc[mt][nt], al[mt], bh[nt>>1][(nt&1)*2], bh[nt>>1][(nt&1)*2+1]);
            }
            // hl (Ah x Bl)
            {
                uint32_t bl[2][4];
                #pragma unroll
                for (int h = 0; h < 2; h++) LDSM4(bl[h], sBl + boff[h] + kB);
                #pragma unroll
                for (int mt = 0; mt < 4; mt++)
                    #pragma unroll
                    for (int nt = 0; nt < 4; nt++)
                        MMA16816(acc[mt][nt], ah[mt], bl[nt>>1][(nt&1)*2], bl[nt>>1][(nt&1)*2+1]);
            }
        }
    }

    // Epilogue: lane (g,t) owns rows (g, g+8), cols (t*2, t*2+1) of each tile
    const int g = lane >> 2, t = (lane & 3) * 2;
    #pragma unroll
    for (int mt = 0; mt < 4; mt++) {
        #pragma unroll
        for (int nt = 0; nt < 4; nt++) {
            int m = m0 + wm + mt * 16 + g;
            int n = n0 + wn + nt * 8 + t;
            float b0v = bias[n], b1v = bias[n + 1];
            #pragma unroll
            for (int rr = 0; rr < 2; rr++) {
                int mr = m + rr * 8;
                float2 val = make_float2(acc[mt][nt][rr*2] + b0v,
                                         acc[mt][nt][rr*2+1] + b1v);
                float* dst;
                if (mode == 0) {
                    dst = out + (size_t)mr * Ee + n;
                } else {
                    int b = mr >> 11, s = mr & 2047;
                    int h = n >> 6, d0 = n & 63;
                    dst = out + (((size_t)(b * Hh + h) * Ss) + s) * Dd + d0;
                }
                *(float2*)dst = val;
            }
        }
    }
}

// ---------------------------------------------------------------------------
// RoPE: table + apply
// ---------------------------------------------------------------------------
__global__ __launch_bounds__(256)
void rope_table_kernel(float* __restrict__ cosT, float* __restrict__ sinT)
{
    int idx = blockIdx.x * 256 + threadIdx.x;
    int j = idx & 31;
    int s = idx >> 5;
    double inv = exp(-((double)(2 * j) / 64.0) * log(10000.0));
    double sd, cd;
    sincos((double)s * inv, &sd, &cd);
    cosT[idx] = (float)cd;
    sinT[idx] = (float)sd;
}

__global__ __launch_bounds__(256)
void rope_apply_kernel(float* __restrict__ q, float* __restrict__ k,
                       const float* __restrict__ cosT, const float* __restrict__ sinT)
{
    int idx = blockIdx.x * 256 + threadIdx.x;
    int jg  = (idx & 7) * 4;
    int row = idx >> 3;
    int s   = row & (Ss - 1);
    float* base = (blockIdx.y == 0 ? q : k) + (size_t)row * Dd;

    float4 c  = *(const float4*)(cosT + s * 32 + jg);
    float4 sn = *(const float4*)(sinT + s * 32 + jg);
    float4 x1 = *(const float4*)(base + jg);
    float4 x2 = *(const float4*)(base + jg + 32);

    float4 r1, r2;
    r1.x = x1.x*c.x - x2.x*sn.x;  r2.x = x2.x*c.x + x1.x*sn.x;
    r1.y = x1.y*c.y - x2.y*sn.y;  r2.y = x2.y*c.y + x1.y*sn.y;
    r1.z = x1.z*c.z - x2.z*sn.z;  r2.z = x2.z*c.z + x1.z*sn.z;
    r1.w = x1.w*c.w - x2.w*sn.w;  r2.w = x2.w*c.w + x1.w*sn.w;

    *(float4*)(base + jg)      = r1;
    *(float4*)(base + jg + 32) = r2;
}

// ---------------------------------------------------------------------------
// Flash attention fp32, causal (unchanged from best-passing R2 kernel).
// ---------------------------------------------------------------------------
__device__ __forceinline__ int swz(int d, int c) {
    return d * 64 + (((( (c >> 2) ^ ((d >> 2) & 15) )) << 2) | (c & 3));
}
__device__ __forceinline__ float4 ld4s(const float* base, int d, int cg) {
    return *(const float4*)(base + d * 64 + ((cg ^ ((d >> 2) & 15)) << 2));
}

__global__ __launch_bounds__(256)
void flash_kernel(const float* __restrict__ q, const float* __restrict__ k,
                  const float* __restrict__ v, float* __restrict__ out)
{
    extern __shared__ float sm[];
    float* Qt   = sm;
    float* KtPt = sm + 4096;
    float* Vs   = sm + 8192;

    const int tid = threadIdx.x;
    const int tx = tid & 15, ty = tid >> 4;
    const int qt = blockIdx.x, bh = blockIdx.y;
    const int q0 = qt * 64;

    const float* qg = q + ((size_t)bh * Ss + q0) * Dd;
    const float* kg = k + (size_t)bh * Ss * Dd;
    const float* vg = v + (size_t)bh * Ss * Dd;

    #pragma unroll
    for (int i = 0; i < 4; i++) {
        int f = i * 256 + tid;
        int c = f >> 4;
        int d0 = (f & 15) * 4;
        float4 t4 = *(const float4*)(qg + c * 64 + d0);
        Qt[swz(d0+0, c)] = t4.x; Qt[swz(d0+1, c)] = t4.y;
        Qt[swz(d0+2, c)] = t4.z; Qt[swz(d0+3, c)] = t4.w;
    }

    float o[4][4];
    float mrow[4], lrow[4];
    #pragma unroll
    for (int i = 0; i < 4; i++) {
        mrow[i] = -1e30f; lrow[i] = 0.f;
        #pragma unroll
        for (int j = 0; j < 4; j++) o[i][j] = 0.f;
    }

    const int ntiles = qt + 1;
    for (int it = 0; it < ntiles; it++) {
        const int kv0 = it * 64;
        __syncthreads();
        #pragma unroll
        for (int i = 0; i < 4; i++) {
            int f = i * 256 + tid;
            int c = f >> 4;
            int d0 = (f & 15) * 4;
            float4 kk4 = *(const float4*)(kg + (size_t)(kv0 + c) * 64 + d0);
            KtPt[swz(d0+0, c)] = kk4.x; KtPt[swz(d0+1, c)] = kk4.y;
            KtPt[swz(d0+2, c)] = kk4.z; KtPt[swz(d0+3, c)] = kk4.w;
            float4 vv4 = *(const float4*)(vg + (size_t)(kv0 + c) * 64 + d0);
            *(float4*)(Vs + c * 64 + d0) = vv4;
        }
        __syncthreads();

        float acc[4][4];
        #pragma unroll
        for (int i = 0; i < 4; i++)
            #pragma unroll
            for (int j = 0; j < 4; j++) acc[i][j] = 0.f;

        #pragma unroll 16
        for (int dd = 0; dd < 64; dd++) {
            float4 a = ld4s(Qt, dd, ty);
            float4 b = ld4s(KtPt, dd, tx);
            acc[0][0] = fmaf(a.x, b.x, acc[0][0]); acc[0][1] = fmaf(a.x, b.y, acc[0][1]);
            acc[0][2] = fmaf(a.x, b.z, acc[0][2]); acc[0][3] = fmaf(a.x, b.w, acc[0][3]);
            acc[1][0] = fmaf(a.y, b.x, acc[1][0]); acc[1][1] = fmaf(a.y, b.y, acc[1][1]);
            acc[1][2] = fmaf(a.y, b.z, acc[1][2]); acc[1][3] = fmaf(a.y, b.w, acc[1][3]);
            acc[2][0] = fmaf(a.z, b.x, acc[2][0]); acc[2][1] = fmaf(a.z, b.y, acc[2][1]);
            acc[2][2] = fmaf(a.z, b.z, acc[2][2]); acc[2][3] = fmaf(a.z, b.w, acc[2][3]);
            acc[3][0] = fmaf(a.w, b.x, acc[3][0]); acc[3][1] = fmaf(a.w, b.y, acc[3][1]);
            acc[3][2] = fmaf(a.w, b.z, acc[3][2]); acc[3][3] = fmaf(a.w, b.w, acc[3][3]);
        }

        const bool diag = (it == qt);
        #pragma unroll
        for (int i = 0; i < 4; i++)
            #pragma unroll
            for (int j = 0; j < 4; j++) {
                float sc = acc[i][j] * 0.125f;
                if (diag && (kv0 + tx*4 + j) > (q0 + ty*4 + i)) sc = -1e30f;
                acc[i][j] = sc;
            }

        float fac[4];
        #pragma unroll
        for (int i = 0; i < 4; i++) {
            float r = fmaxf(fmaxf(acc[i][0], acc[i][1]), fmaxf(acc[i][2], acc[i][3]));
            #pragma unroll
            for (int off = 1; off < 16; off <<= 1)
                r = fmaxf(r, __shfl_xor_sync(0xffffffffu, r, off));
            float mnew = fmaxf(mrow[i], r);
            fac[i] = __expf(mrow[i] - mnew);
            #pragma unroll
            for (int j = 0; j < 4; j++) acc[i][j] = __expf(acc[i][j] - mnew);
            float rs = acc[i][0] + acc[i][1] + acc[i][2] + acc[i][3];
            #pragma unroll
            for (int off = 1; off < 16; off <<= 1)
                rs += __shfl_xor_sync(0xffffffffu, rs, off);
            lrow[i] = lrow[i] * fac[i] + rs;
            mrow[i] = mnew;
            #pragma unroll
            for (int j = 0; j < 4; j++) o[i][j] *= fac[i];
        }

        __syncthreads();
        #pragma unroll
        for (int jj = 0; jj < 4; jj++) {
            int t = tx * 4 + jj;
            float4 pv = make_float4(acc[0][jj], acc[1][jj], acc[2][jj], acc[3][jj]);
            *(float4*)(KtPt + t * 64 + ((ty ^ ((t >> 2) & 15)) << 2)) = pv;
        }
        __syncthreads();

        #pragma unroll 16
        for (int t = 0; t < 64; t++) {
            float4 a = ld4s(KtPt, t, ty);
            float4 b = *(const float4*)(Vs + t * 64 + tx * 4);
            o[0][0] = fmaf(a.x, b.x, o[0][0]); o[0][1] = fmaf(a.x, b.y, o[0][1]);
            o[0][2] = fmaf(a.x, b.z, o[0][2]); o[0][3] = fmaf(a.x, b.w, o[0][3]);
            o[1][0] = fmaf(a.y, b.x, o[1][0]); o[1][1] = fmaf(a.y, b.y, o[1][1]);
            o[1][2] = fmaf(a.y, b.z, o[1][2]); o[1][3] = fmaf(a.y, b.w, o[1][3]);
            o[2][0] = fmaf(a.z, b.x, o[2][0]); o[2][1] = fmaf(a.z, b.y, o[2][1]);
            o[2][2] = fmaf(a.z, b.z, o[2][2]); o[2][3] = fmaf(a.z, b.w, o[2][3]);
            o[3][0] = fmaf(a.w, b.x, o[3][0]); o[3][1] = fmaf(a.w, b.y, o[3][1]);
            o[3][2] = fmaf(a.w, b.z, o[3][2]); o[3][3] = fmaf(a.w, b.w, o[3][3]);
        }
    }

    const int b = bh >> 4, h = bh & 15;
    #pragma unroll
    for (int i = 0; i < 4; i++) {
        int s = q0 + ty * 4 + i;
        float il = 1.0f / lrow[i];
        float4 r = make_float4(o[i][0]*il, o[i][1]*il, o[i][2]*il, o[i][3]*il);
        *(float4*)(out + ((size_t)(b * Ss + s)) * Ee + h * 64 + tx * 4) = r;
    }
}

// ---------------------------------------------------------------------------
extern "C" void kernel_launch(void* const* d_in, const int* in_sizes, int n_in,
                              void* d_out, int out_size)
{
    (void)in_sizes; (void)n_in; (void)out_size;
    const float* query = (const float*)d_in[0];
    const float* key   = (const float*)d_in[1];
    const float* value = (const float*)d_in[2];
    const float* Wq = (const float*)d_in[3];
    const float* bq = (const float*)d_in[4];
    const float* Wk = (const float*)d_in[5];
    const float* bk = (const float*)d_in[6];
    const float* Wv = (const float*)d_in[7];
    const float* bv = (const float*)d_in[8];
    const float* Wo = (const float*)d_in[9];
    const float* bo = (const float*)d_in[10];
    float* out = (float*)d_out;

    float *qp, *kp, *vp, *aop, *ct, *st;
    __nv_bfloat16 *xh, *xl, *wh, *wl;
    cudaGetSymbolAddress((void**)&qp,  g_q);
    cudaGetSymbolAddress((void**)&kp,  g_k);
    cudaGetSymbolAddress((void**)&vp,  g_v);
    cudaGetSymbolAddress((void**)&aop, g_ao);
    cudaGetSymbolAddress((void**)&ct,  g_cos);
    cudaGetSymbolAddress((void**)&st,  g_sin);
    cudaGetSymbolAddress((void**)&xh,  g_xh);
    cudaGetSymbolAddress((void**)&xl,  g_xl);
    cudaGetSymbolAddress((void**)&wh,  g_wh);
    cudaGetSymbolAddress((void**)&wl,  g_wl);

    cudaFuncSetAttribute(flash_kernel,
                         cudaFuncAttributeMaxDynamicSharedMemorySize, 49152);
    cudaFuncSetAttribute(tgemm,
                         cudaFuncAttributeMaxDynamicSharedMemorySize, TG_SMEM);

    const int WBLK = (Ee * Ee / 4) / 256;   // 1024
    const int XBLK = (Mm * Ee / 4) / 256;   // 4096
    dim3 gg(Ee / 128, Mm / 128);            // (8, 32)

    rope_table_kernel<<<(Ss * 32) / 256, 256>>>(ct, st);

    split_kernel<<<WBLK, 256>>>(Wq, wh, wl);
    split_kernel<<<XBLK, 256>>>(query, xh, xl);
    tgemm<<<gg, 256, TG_SMEM>>>(xh, xl, wh, wl, bq, qp, 1);

    split_kernel<<<WBLK, 256>>>(Wk, wh, wl);
    split_kernel<<<XBLK, 256>>>(key, xh, xl);
    tgemm<<<gg, 256, TG_SMEM>>>(xh, xl, wh, wl, bk, kp, 1);

    split_kernel<<<WBLK, 256>>>(Wv, wh, wl);
    split_kernel<<<XBLK, 256>>>(value, xh, xl);
    tgemm<<<gg, 256, TG_SMEM>>>(xh, xl, wh, wl, bv, vp, 1);

    int ropeBlocks = (Bb * Hh * Ss * 8) / 256;
    rope_apply_kernel<<<dim3(ropeBlocks, 2), 256>>>(qp, kp, ct, st);

    flash_kernel<<<dim3(Ss / 64, Bb * Hh), 256, 49152>>>(qp, kp, vp, aop);

    split_kernel<<<WBLK, 256>>>(Wo, wh, wl);
    split_kernel<<<XBLK, 256>>>(aop, xh, xl);
    tgemm<<<gg, 256, TG_SMEM>>>(xh, xl, wh, wl, bo, out, 0);
}

// round 8
// speedup vs baseline: 3.9591x; 1.7916x over previous
#include <cuda_runtime.h>
#include <cuda_bf16.h>
#include <math.h>
#include <stdint.h>

#define Bb 2
#define Ss 2048
#define Ee 1024
#define Hh 16
#define Dd 64
#define Mm (Bb*Ss)   // 4096

// Scratch (allocation-free rule: __device__ globals)
__device__ float g_q[Bb*Hh*Ss*Dd];
__device__ float g_k[Bb*Hh*Ss*Dd];
__device__ float g_v[Bb*Hh*Ss*Dd];
__device__ float g_ao[Bb*Ss*Ee];
__device__ float g_cos[Ss*32];
__device__ float g_sin[Ss*32];
__device__ __nv_bfloat16 g_xh[Mm*Ee];
__device__ __nv_bfloat16 g_xl[Mm*Ee];
__device__ __nv_bfloat16 g_wh[Ee*Ee];
__device__ __nv_bfloat16 g_wl[Ee*Ee];
__device__ __nv_bfloat16 g_qh[Bb*Hh*Ss*Dd];
__device__ __nv_bfloat16 g_ql[Bb*Hh*Ss*Dd];
__device__ __nv_bfloat16 g_kh[Bb*Hh*Ss*Dd];
__device__ __nv_bfloat16 g_kl[Bb*Hh*Ss*Dd];
__device__ __nv_bfloat16 g_vth[Bb*Hh*Dd*Ss];
__device__ __nv_bfloat16 g_vtl[Bb*Hh*Dd*Ss];

// ---------------------------------------------------------------------------
// Helpers (plain sm_80-class PTX only: mma.sync / ldmatrix / cp.async)
// ---------------------------------------------------------------------------
__device__ __forceinline__ uint32_t smem_to_u32(const void* p) {
    uint32_t a;
    asm("{ .reg .u64 t; cvta.to.shared.u64 t, %1; cvt.u32.u64 %0, t; }" : "=r"(a) : "l"(p));
    return a;
}
#define CP_ASYNC16(dst, src) \
    asm volatile("cp.async.cg.shared.global [%0], [%1], 16;" :: "r"(dst), "l"(src))
#define CP_ASYNC_COMMIT() asm volatile("cp.async.commit_group;" ::: "memory")
#define CP_ASYNC_WAIT0()  asm volatile("cp.async.wait_group 0;" ::: "memory")
#define SWZ128(o) ((o) ^ (((o) >> 3) & 0x70))

#define LDSM4(r, addr) \
    asm volatile("ldmatrix.sync.aligned.m8n8.x4.shared.b16 {%0,%1,%2,%3}, [%4];" \
        : "=r"((r)[0]), "=r"((r)[1]), "=r"((r)[2]), "=r"((r)[3]) : "r"(addr))

#define MMA16816(c, a, b0, b1) \
    asm volatile("mma.sync.aligned.m16n8k16.row.col.f32.bf16.bf16.f32 " \
        "{%0,%1,%2,%3},{%4,%5,%6,%7},{%8,%9},{%0,%1,%2,%3};" \
        : "+f"((c)[0]), "+f"((c)[1]), "+f"((c)[2]), "+f"((c)[3]) \
        : "r"((a)[0]), "r"((a)[1]), "r"((a)[2]), "r"((a)[3]), "r"(b0), "r"(b1))

// pack two fp32 -> bf16x2 register (lo = first arg, hi = second)
__device__ __forceinline__ uint32_t bf2pack(float lo, float hi) {
    uint32_t r;
    asm("cvt.rn.bf16x2.f32 %0, %1, %2;" : "=r"(r) : "f"(hi), "f"(lo));
    return r;
}

// fast e^x on FMA pipe (x <= 0 expected; handles -1e30 masks via clamp)
__device__ __forceinline__ float fexp(float x) {
    x = fmaxf(x, -87.0f);
    float z = x * 1.4426950408889634f;
    float t = z + 12582912.0f;
    float n = t - 12582912.0f;
    float f = z - n;
    float p = 1.3333558146e-3f;
    p = fmaf(p, f, 9.6181291907e-3f);
    p = fmaf(p, f, 5.5504108664e-2f);
    p = fmaf(p, f, 2.4022650696e-1f);
    p = fmaf(p, f, 6.9314718056e-1f);
    p = fmaf(p, f, 1.0f);
    float sc = __uint_as_float((__float_as_uint(t) << 23) + 0x3F800000u);
    return p * sc;
}

// ---------------------------------------------------------------------------
// Split fp32 -> (hi, lo) bf16. One thread per 4 elements.
// ---------------------------------------------------------------------------
__global__ __launch_bounds__(256)
void split_kernel(const float* __restrict__ x, __nv_bfloat16* __restrict__ hi,
                  __nv_bfloat16* __restrict__ lo)
{
    int i = blockIdx.x * 256 + threadIdx.x;
    float4 v = ((const float4*)x)[i];
    uint32_t h01 = bf2pack(v.x, v.y), h23 = bf2pack(v.z, v.w);
    float f0 = __uint_as_float(h01 << 16), f1 = __uint_as_float(h01 & 0xFFFF0000u);
    float f2 = __uint_as_float(h23 << 16), f3 = __uint_as_float(h23 & 0xFFFF0000u);
    uint32_t l01 = bf2pack(v.x - f0, v.y - f1), l23 = bf2pack(v.z - f2, v.w - f3);
    ((uint2*)hi)[i] = make_uint2(h01, h23);
    ((uint2*)lo)[i] = make_uint2(l01, l23);
}

// ---------------------------------------------------------------------------
// HMMA GEMM: out[4096,1024] = X @ W^T + bias, bf16 3-term split (hh+lh+hl).
// CTA tile 128x128, K-chunk 64. 8 warps in 2x4 grid, warp tile 64x32.
// mode 0: row-major out; mode 1: scatter to [B,H,S,D].
// ---------------------------------------------------------------------------
#define TG_SMEM 65536

__global__ __launch_bounds__(256, 2)
void tgemm(const __nv_bfloat16* __restrict__ Ahp, const __nv_bfloat16* __restrict__ Alp,
           const __nv_bfloat16* __restrict__ Bhp, const __nv_bfloat16* __restrict__ Blp,
           const float* __restrict__ bias, float* __restrict__ out, int mode)
{
    extern __shared__ char smem[];
    uint32_t sb = smem_to_u32(smem);
    const int tid = threadIdx.x;
    const int lane = tid & 31, wid = tid >> 5;
    const int m0 = blockIdx.y * 128, n0 = blockIdx.x * 128;
    const int wm = (wid >> 2) * 64, wn = (wid & 3) * 32;

    const uint32_t sA  = sb;
    const uint32_t sAl = sb + 16384;
    const uint32_t sB  = sb + 32768;
    const uint32_t sBl = sb + 49152;

    float acc[4][4][4];
    #pragma unroll
    for (int mt = 0; mt < 4; mt++)
        #pragma unroll
        for (int nt = 0; nt < 4; nt++)
            #pragma unroll
            for (int r = 0; r < 4; r++) acc[mt][nt][r] = 0.f;

    const int lr = lane & 15;
    const uint32_t akb = (lane >> 4) * 16;
    const uint32_t xrA = (uint32_t)(lr & 7) << 4;
    const int brow = (lane & 7) + ((lane >> 1) & 8);
    const uint32_t bkb = (uint32_t)(lane & 8) * 2;
    const uint32_t xrB = (uint32_t)(lane & 7) << 4;

    uint32_t aoff[4], boff[2];
    #pragma unroll
    for (int mt = 0; mt < 4; mt++) aoff[mt] = (uint32_t)(wm + mt * 16 + lr) * 128;
    #pragma unroll
    for (int h = 0; h < 2; h++)    boff[h]  = (uint32_t)(wn + h * 16 + brow) * 128;

    const char* srcs[4] = {(const char*)Ahp, (const char*)Alp,
                           (const char*)Bhp, (const char*)Blp};
    const uint32_t dsts[4] = {sA, sAl, sB, sBl};
    const int r0s[4] = {m0, m0, n0, n0};

    for (int kc = 0; kc < 16; kc++) {
        if (kc) __syncthreads();
        #pragma unroll
        for (int arr = 0; arr < 4; arr++) {
            #pragma unroll
            for (int i = 0; i < 4; i++) {
                int p = i * 256 + tid;
                int r = p >> 3, c = (p & 7) * 16;
                uint32_t dst = dsts[arr] + SWZ128((uint32_t)(r * 128 + c));
                const char* src = srcs[arr] + ((size_t)(r0s[arr] + r)) * 2048
                                  + kc * 128 + c;
                CP_ASYNC16(dst, src);
            }
        }
        CP_ASYNC_COMMIT();
        CP_ASYNC_WAIT0();
        __syncthreads();

        #pragma unroll
        for (int s = 0; s < 4; s++) {
            const uint32_t kA = ((uint32_t)(s * 32) + akb) ^ xrA;
            const uint32_t kB = ((uint32_t)(s * 32) + bkb) ^ xrB;

            uint32_t ah[4][4], bh[2][4];
            #pragma unroll
            for (int mt = 0; mt < 4; mt++) LDSM4(ah[mt], sA + aoff[mt] + kA);
            #pragma unroll
            for (int h = 0; h < 2; h++)    LDSM4(bh[h],  sB + boff[h] + kB);

            #pragma unroll
            for (int mt = 0; mt < 4; mt++)
                #pragma unroll
                for (int nt = 0; nt < 4; nt++)
                    MMA16816(acc[mt][nt], ah[mt], bh[nt>>1][(nt&1)*2], bh[nt>>1][(nt&1)*2+1]);

            {
                uint32_t al[4][4];
                #pragma unroll
                for (int mt = 0; mt < 4; mt++) LDSM4(al[mt], sAl + aoff[mt] + kA);
                #pragma unroll
                for (int mt = 0; mt < 4; mt++)
                    #pragma unroll
                    for (int nt = 0; nt < 4; nt++)
                        MMA16816(acc[mt][nt], al[mt], bh[nt>>1][(nt&1)*2], bh[nt>>1][(nt&1)*2+1]);
            }
            {
                uint32_t bl[2][4];
                #pragma unroll
                for (int h = 0; h < 2; h++) LDSM4(bl[h], sBl + boff[h] + kB);
                #pragma unroll
                for (int mt = 0; mt < 4; mt++)
                    #pragma unroll
                    for (int nt = 0; nt < 4; nt++)
                        MMA16816(acc[mt][nt], ah[mt], bl[nt>>1][(nt&1)*2], bl[nt>>1][(nt&1)*2+1]);
            }
        }
    }

    const int g = lane >> 2, t = (lane & 3) * 2;
    #pragma unroll
    for (int mt = 0; mt < 4; mt++) {
        #pragma unroll
        for (int nt = 0; nt < 4; nt++) {
            int m = m0 + wm + mt * 16 + g;
            int n = n0 + wn + nt * 8 + t;
            float b0v = bias[n], b1v = bias[n + 1];
            #pragma unroll
            for (int rr = 0; rr < 2; rr++) {
                int mr = m + rr * 8;
                float2 val = make_float2(acc[mt][nt][rr*2] + b0v,
                                         acc[mt][nt][rr*2+1] + b1v);
                float* dst;
                if (mode == 0) {
                    dst = out + (size_t)mr * Ee + n;
                } else {
                    int b = mr >> 11, s = mr & 2047;
                    int h = n >> 6, d0 = n & 63;
                    dst = out + (((size_t)(b * Hh + h) * Ss) + s) * Dd + d0;
                }
                *(float2*)dst = val;
            }
        }
    }
}

// ---------------------------------------------------------------------------
// RoPE: table + apply(with bf16 split output)
// ---------------------------------------------------------------------------
__global__ __launch_bounds__(256)
void rope_table_kernel(float* __restrict__ cosT, float* __restrict__ sinT)
{
    int idx = blockIdx.x * 256 + threadIdx.x;
    int j = idx & 31;
    int s = idx >> 5;
    double inv = exp(-((double)(2 * j) / 64.0) * log(10000.0));
    double sd, cd;
    sincos((double)s * inv, &sd, &cd);
    cosT[idx] = (float)cd;
    sinT[idx] = (float)sd;
}

__global__ __launch_bounds__(256)
void rope_apply_split(const float* __restrict__ qp, const float* __restrict__ kp,
                      __nv_bfloat16* __restrict__ qh, __nv_bfloat16* __restrict__ ql,
                      __nv_bfloat16* __restrict__ kh, __nv_bfloat16* __restrict__ kl,
                      const float* __restrict__ cosT, const float* __restrict__ sinT)
{
    int idx = blockIdx.x * 256 + threadIdx.x;
    int jg  = (idx & 7) * 4;
    int row = idx >> 3;
    int s   = row & (Ss - 1);
    const float* src = (blockIdx.y == 0 ? qp : kp) + (size_t)row * Dd;
    __nv_bfloat16* dh = (blockIdx.y == 0 ? qh : kh) + (size_t)row * Dd;
    __nv_bfloat16* dl = (blockIdx.y == 0 ? ql : kl) + (size_t)row * Dd;

    float4 c  = *(const float4*)(cosT + s * 32 + jg);
    float4 sn = *(const float4*)(sinT + s * 32 + jg);
    float4 x1 = *(const float4*)(src + jg);
    float4 x2 = *(const float4*)(src + jg + 32);

    float r1[4], r2[4];
    r1[0] = x1.x*c.x - x2.x*sn.x;  r2[0] = x2.x*c.x + x1.x*sn.x;
    r1[1] = x1.y*c.y - x2.y*sn.y;  r2[1] = x2.y*c.y + x1.y*sn.y;
    r1[2] = x1.z*c.z - x2.z*sn.z;  r2[2] = x2.z*c.z + x1.z*sn.z;
    r1[3] = x1.w*c.w - x2.w*sn.w;  r2[3] = x2.w*c.w + x1.w*sn.w;

    #pragma unroll
    for (int half = 0; half < 2; half++) {
        float* r = half ? r2 : r1;
        int off = jg + half * 32;
        uint32_t h01 = bf2pack(r[0], r[1]), h23 = bf2pack(r[2], r[3]);
        float f0 = __uint_as_float(h01 << 16), f1 = __uint_as_float(h01 & 0xFFFF0000u);
        float f2 = __uint_as_float(h23 << 16), f3 = __uint_as_float(h23 & 0xFFFF0000u);
        uint32_t l01 = bf2pack(r[0]-f0, r[1]-f1), l23 = bf2pack(r[2]-f2, r[3]-f3);
        *(uint32_t*)(dh + off)     = h01;
        *(uint32_t*)(dh + off + 2) = h23;
        *(uint32_t*)(dl + off)     = l01;
        *(uint32_t*)(dl + off + 2) = l23;
    }
}

// ---------------------------------------------------------------------------
// V convert: fp32 [B,H,S,D] -> split bf16 transposed [B,H,D,S]
// ---------------------------------------------------------------------------
__global__ __launch_bounds__(256)
void vconvert(const float* __restrict__ v, __nv_bfloat16* __restrict__ vth,
              __nv_bfloat16* __restrict__ vtl)
{
    __shared__ float sm[64][65];
    const int s0 = blockIdx.x * 64, bh = blockIdx.y;
    const int tid = threadIdx.x;
    const float* src = v + ((size_t)bh * Ss + s0) * Dd;
    #pragma unroll
    for (int i = 0; i < 16; i++) {
        int p = tid + i * 256;
        int r = p >> 6, c = p & 63;
        sm[c][r] = src[(size_t)r * Dd + c];
    }
    __syncthreads();
    #pragma unroll
    for (int i = 0; i < 8; i++) {
        int pp = tid + i * 256;           // 0..2047
        int d = pp >> 5, sp = (pp & 31) * 2;
        float v0 = sm[d][sp], v1 = sm[d][sp + 1];
        uint32_t hp = bf2pack(v0, v1);
        float f0 = __uint_as_float(hp << 16), f1 = __uint_as_float(hp & 0xFFFF0000u);
        uint32_t lp = bf2pack(v0 - f0, v1 - f1);
        size_t off = ((size_t)(bh * Dd + d)) * Ss + s0 + sp;
        *(uint32_t*)(vth + off) = hp;
        *(uint32_t*)(vtl + off) = lp;
    }
}

// ---------------------------------------------------------------------------
// Flash attention, HMMA bf16 3-term split, causal.
// Block = 128 q rows, 8 warps (warp = m16, full kv width 64). KV tile 64.
// ---------------------------------------------------------------------------
#define FL_SMEM 65536

__global__ __launch_bounds__(256)
void flash_mma(const __nv_bfloat16* __restrict__ qhp, const __nv_bfloat16* __restrict__ qlp,
               const __nv_bfloat16* __restrict__ khp, const __nv_bfloat16* __restrict__ klp,
               const __nv_bfloat16* __restrict__ vthp, const __nv_bfloat16* __restrict__ vtlp,
               float* __restrict__ out)
{
    extern __shared__ char smem[];
    uint32_t sb = smem_to_u32(smem);
    const uint32_t sQh = sb,          sQl = sb + 16384;
    const uint32_t sKh = sb + 32768,  sKl = sb + 40960;
    const uint32_t sVh = sb + 49152,  sVl = sb + 57344;

    const int tid = threadIdx.x, lane = tid & 31, wid = tid >> 5;
    const int qt = (int)gridDim.x - 1 - (int)blockIdx.x;   // heavy tiles first
    const int bh = blockIdx.y;
    const int q0 = qt * 128;
    const int wm = wid * 16;

    // stage Q (hi+lo)
    {
        const char* gq  = (const char*)qhp + ((size_t)(bh * Ss + q0)) * 128;
        const char* gql = (const char*)qlp + ((size_t)(bh * Ss + q0)) * 128;
        #pragma unroll
        for (int i = 0; i < 4; i++) {
            int p = i * 256 + tid;
            int r = p >> 3, c = (p & 7) * 16;
            uint32_t o1 = SWZ128((uint32_t)(r * 128 + c));
            CP_ASYNC16(sQh + o1, gq  + (size_t)r * 128 + c);
            CP_ASYNC16(sQl + o1, gql + (size_t)r * 128 + c);
        }
        CP_ASYNC_COMMIT(); CP_ASYNC_WAIT0();
    }
    __syncthreads();

    // Q fragments -> registers
    const uint32_t xr  = (uint32_t)(lane & 7) << 4;
    const uint32_t akb = (uint32_t)(lane >> 4) * 16;
    const uint32_t arow = (uint32_t)(wm + (lane & 15)) * 128;
    uint32_t aQh[4][4], aQl[4][4];
    #pragma unroll
    for (int s = 0; s < 4; s++) {
        uint32_t kA = ((uint32_t)(s * 32) + akb) ^ xr;
        LDSM4(aQh[s], sQh + arow + kA);
        LDSM4(aQl[s], sQl + arow + kA);
    }

    const int brow = (lane & 7) + ((lane >> 1) & 8);
    const uint32_t bkb = (uint32_t)(lane & 8) * 2;
    uint32_t boffs[4];
    #pragma unroll
    for (int p = 0; p < 4; p++) boffs[p] = (uint32_t)(p * 16 + brow) * 128;

    float o[8][4];
    #pragma unroll
    for (int nt = 0; nt < 8; nt++)
        #pragma unroll
        for (int r = 0; r < 4; r++) o[nt][r] = 0.f;
    float mv[2] = {-1e30f, -1e30f}, lv[2] = {0.f, 0.f};

    const int g = lane >> 2, tq = (lane & 3) * 2;
    const int ntiles = 2 * qt + 2;

    for (int it = 0; it < ntiles; it++) {
        const int kv0 = it * 64;
        __syncthreads();
        {
            const char* gkh = (const char*)khp  + ((size_t)(bh * Ss + kv0)) * 128;
            const char* gkl = (const char*)klp  + ((size_t)(bh * Ss + kv0)) * 128;
            const char* gvh = (const char*)vthp + (((size_t)bh * Dd) * Ss + kv0) * 2;
            const char* gvl = (const char*)vtlp + (((size_t)bh * Dd) * Ss + kv0) * 2;
            #pragma unroll
            for (int i = 0; i < 2; i++) {
                int p = i * 256 + tid;
                int r = p >> 3, c = (p & 7) * 16;
                uint32_t o1 = SWZ128((uint32_t)(r * 128 + c));
                CP_ASYNC16(sKh + o1, gkh + (size_t)r * 128 + c);
                CP_ASYNC16(sKl + o1, gkl + (size_t)r * 128 + c);
                CP_ASYNC16(sVh + o1, gvh + (size_t)r * (Ss * 2) + c);
                CP_ASYNC16(sVl + o1, gvl + (size_t)r * (Ss * 2) + c);
            }
            CP_ASYNC_COMMIT(); CP_ASYNC_WAIT0();
        }
        __syncthreads();

        // S = Q K^T  (3 terms)
        float acc[8][4];
        #pragma unroll
        for (int nt = 0; nt < 8; nt++)
            #pragma unroll
            for (int r = 0; r < 4; r++) acc[nt][r] = 0.f;

        #pragma unroll
        for (int s = 0; s < 4; s++) {
            uint32_t kB = ((uint32_t)(s * 32) + bkb) ^ xr;
            uint32_t bKh[4][4], bKl[4][4];
            #pragma unroll
            for (int p = 0; p < 4; p++) LDSM4(bKh[p], sKh + boffs[p] + kB);
            #pragma unroll
            for (int p = 0; p < 4; p++) LDSM4(bKl[p], sKl + boffs[p] + kB);
            #pragma unroll
            for (int p = 0; p < 4; p++) {
                MMA16816(acc[2*p],   aQh[s], bKh[p][0], bKh[p][1]);
                MMA16816(acc[2*p+1], aQh[s], bKh[p][2], bKh[p][3]);
                MMA16816(acc[2*p],   aQl[s], bKh[p][0], bKh[p][1]);
                MMA16816(acc[2*p+1], aQl[s], bKh[p][2], bKh[p][3]);
                MMA16816(acc[2*p],   aQh[s], bKl[p][0], bKl[p][1]);
                MMA16816(acc[2*p+1], aQh[s], bKl[p][2], bKl[p][3]);
            }
        }

        // scale + causal mask
        const int row0 = q0 + wm + g;
        if (it >= 2 * qt) {
            #pragma unroll
            for (int nt = 0; nt < 8; nt++) {
                int col = kv0 + nt * 8 + tq;
                #pragma unroll
                for (int r = 0; r < 4; r++) {
                    int cc = col + (r & 1);
                    int rr = row0 + (r >= 2 ? 8 : 0);
                    acc[nt][r] = (cc > rr) ? -1e30f : acc[nt][r] * 0.125f;
                }
            }
        } else {
            #pragma unroll
            for (int nt = 0; nt < 8; nt++)
                #pragma unroll
                for (int r = 0; r < 4; r++) acc[nt][r] *= 0.125f;
        }

        // online softmax (poly exp on FMA pipe)
        #pragma unroll
        for (int h = 0; h < 2; h++) {
            float rmax = -1e30f;
            #pragma unroll
            for (int nt = 0; nt < 8; nt++)
                rmax = fmaxf(rmax, fmaxf(acc[nt][2*h], acc[nt][2*h+1]));
            rmax = fmaxf(rmax, __shfl_xor_sync(0xffffffffu, rmax, 1));
            rmax = fmaxf(rmax, __shfl_xor_sync(0xffffffffu, rmax, 2));
            float mnew = fmaxf(mv[h], rmax);
            float fac = fexp(mv[h] - mnew);
            float rs = 0.f;
            #pragma unroll
            for (int nt = 0; nt < 8; nt++) {
                acc[nt][2*h]   = fexp(acc[nt][2*h]   - mnew);
                acc[nt][2*h+1] = fexp(acc[nt][2*h+1] - mnew);
                rs += acc[nt][2*h] + acc[nt][2*h+1];
            }
            rs += __shfl_xor_sync(0xffffffffu, rs, 1);
            rs += __shfl_xor_sync(0xffffffffu, rs, 2);
            lv[h] = lv[h] * fac + rs;
            mv[h] = mnew;
            #pragma unroll
            for (int nt = 0; nt < 8; nt++) { o[nt][2*h] *= fac; o[nt][2*h+1] *= fac; }
        }

        // P -> split bf16 A-fragments
        uint32_t aPh[4][4], aPl[4][4];
        #pragma unroll
        for (int ks = 0; ks < 4; ks++) {
            #pragma unroll
            for (int half = 0; half < 2; half++) {      // nt = 2ks (+half)
                int nt = 2 * ks + half;
                #pragma unroll
                for (int rp = 0; rp < 2; rp++) {        // row g / g+8
                    float p0 = acc[nt][2*rp], p1 = acc[nt][2*rp+1];
                    uint32_t hp = bf2pack(p0, p1);
                    float f0 = __uint_as_float(hp << 16);
                    float f1 = __uint_as_float(hp & 0xFFFF0000u);
                    uint32_t lp = bf2pack(p0 - f0, p1 - f1);
                    aPh[ks][half*2 + rp] = hp;
                    aPl[ks][half*2 + rp] = lp;
                }
            }
        }

        // O += P V  (3 terms)
        #pragma unroll
        for (int s = 0; s < 4; s++) {
            uint32_t kB = ((uint32_t)(s * 32) + bkb) ^ xr;
            uint32_t bVh[4][4], bVl[4][4];
            #pragma unroll
            for (int p = 0; p < 4; p++) LDSM4(bVh[p], sVh + boffs[p] + kB);
            #pragma unroll
            for (int p = 0; p < 4; p++) LDSM4(bVl[p], sVl + boffs[p] + kB);
            #pragma unroll
            for (int p = 0; p < 4; p++) {
                MMA16816(o[2*p],   aPh[s], bVh[p][0], bVh[p][1]);
                MMA16816(o[2*p+1], aPh[s], bVh[p][2], bVh[p][3]);
                MMA16816(o[2*p],   aPl[s], bVh[p][0], bVh[p][1]);
                MMA16816(o[2*p+1], aPl[s], bVh[p][2], bVh[p][3]);
                MMA16816(o[2*p],   aPh[s], bVl[p][0], bVl[p][1]);
                MMA16816(o[2*p+1], aPh[s], bVl[p][2], bVl[p][3]);
            }
        }
    }

    // epilogue: normalize, write [B,S,E]
    const int b = bh >> 4, h = bh & 15;
    float il0 = 1.0f / lv[0], il1 = 1.0f / lv[1];
    const int row0 = q0 + wm + g;
    #pragma unroll
    for (int nt = 0; nt < 8; nt++) {
        int col = h * 64 + nt * 8 + tq;
        float2 v0 = make_float2(o[nt][0] * il0, o[nt][1] * il0);
        float2 v1 = make_float2(o[nt][2] * il1, o[nt][3] * il1);
        *(float2*)(out + ((size_t)(b * Ss + row0)) * Ee + col)     = v0;
        *(float2*)(out + ((size_t)(b * Ss + row0 + 8)) * Ee + col) = v1;
    }
}

// ---------------------------------------------------------------------------
extern "C" void kernel_launch(void* const* d_in, const int* in_sizes, int n_in,
                              void* d_out, int out_size)
{
    (void)in_sizes; (void)n_in; (void)out_size;
    const float* query = (const float*)d_in[0];
    const float* key   = (const float*)d_in[1];
    const float* value = (const float*)d_in[2];
    const float* Wq = (const float*)d_in[3];
    const float* bq = (const float*)d_in[4];
    const float* Wk = (const float*)d_in[5];
    const float* bk = (const float*)d_in[6];
    const float* Wv = (const float*)d_in[7];
    const float* bv = (const float*)d_in[8];
    const float* Wo = (const float*)d_in[9];
    const float* bo = (const float*)d_in[10];
    float* out = (float*)d_out;

    float *qp, *kp, *vp, *aop, *ct, *st;
    __nv_bfloat16 *xh, *xl, *wh, *wl, *qh, *ql, *kh, *kl, *vth, *vtl;
    cudaGetSymbolAddress((void**)&qp,  g_q);
    cudaGetSymbolAddress((void**)&kp,  g_k);
    cudaGetSymbolAddress((void**)&vp,  g_v);
    cudaGetSymbolAddress((void**)&aop, g_ao);
    cudaGetSymbolAddress((void**)&ct,  g_cos);
    cudaGetSymbolAddress((void**)&st,  g_sin);
    cudaGetSymbolAddress((void**)&xh,  g_xh);
    cudaGetSymbolAddress((void**)&xl,  g_xl);
    cudaGetSymbolAddress((void**)&wh,  g_wh);
    cudaGetSymbolAddress((void**)&wl,  g_wl);
    cudaGetSymbolAddress((void**)&qh,  g_qh);
    cudaGetSymbolAddress((void**)&ql,  g_ql);
    cudaGetSymbolAddress((void**)&kh,  g_kh);
    cudaGetSymbolAddress((void**)&kl,  g_kl);
    cudaGetSymbolAddress((void**)&vth, g_vth);
    cudaGetSymbolAddress((void**)&vtl, g_vtl);

    cudaFuncSetAttribute(tgemm,
                         cudaFuncAttributeMaxDynamicSharedMemorySize, TG_SMEM);
    cudaFuncSetAttribute(flash_mma,
                         cudaFuncAttributeMaxDynamicSharedMemorySize, FL_SMEM);

    const int WBLK = (Ee * Ee / 4) / 256;   // 1024
    const int XBLK = (Mm * Ee / 4) / 256;   // 4096
    dim3 gg(Ee / 128, Mm / 128);            // (8, 32)

    rope_table_kernel<<<(Ss * 32) / 256, 256>>>(ct, st);

    split_kernel<<<WBLK, 256>>>(Wq, wh, wl);
    split_kernel<<<XBLK, 256>>>(query, xh, xl);
    tgemm<<<gg, 256, TG_SMEM>>>(xh, xl, wh, wl, bq, qp, 1);

    split_kernel<<<WBLK, 256>>>(Wk, wh, wl);
    split_kernel<<<XBLK, 256>>>(key, xh, xl);
    tgemm<<<gg, 256, TG_SMEM>>>(xh, xl, wh, wl, bk, kp, 1);

    split_kernel<<<WBLK, 256>>>(Wv, wh, wl);
    split_kernel<<<XBLK, 256>>>(value, xh, xl);
    tgemm<<<gg, 256, TG_SMEM>>>(xh, xl, wh, wl, bv, vp, 1);

    int ropeBlocks = (Bb * Hh * Ss * 8) / 256;   // 2048
    rope_apply_split<<<dim3(ropeBlocks, 2), 256>>>(qp, kp, qh, ql, kh, kl, ct, st);

    vconvert<<<dim3(Ss / 64, Bb * Hh), 256>>>(vp, vth, vtl);

    flash_mma<<<dim3(Ss / 128, Bb * Hh), 256, FL_SMEM>>>(qh, ql, kh, kl, vth, vtl, aop);

    split_kernel<<<WBLK, 256>>>(Wo, wh, wl);
    split_kernel<<<XBLK, 256>>>(aop, xh, xl);
    tgemm<<<gg, 256, TG_SMEM>>>(xh, xl, wh, wl, bo, out, 0);
}